// round 3
// baseline (speedup 1.0000x reference)
#include <cuda_runtime.h>
#include <math.h>

#define NB 64
#define BC 16                  // batches per L2-resident chunk (64 MB slab)
#define NCHUNK (NB / BC)
#define NL 1024
#define ND 1024
#define SPLIT 16               // kD l-splits  (CH_D = 64)
#define CH_D (NL / SPLIT)
#define SPLITE 32              // kE l-splits  (CH_E = 32)
#define CH_E (NL / SPLITE)
#define EPSF 1e-15f
#define PROJ_EPS 4e-3f

// ---------------- scratch (device globals) ----------------
__device__ float g_combined[NB * 2 * ND];   // [b,0:D)=mixl, [b,D:2D)=q
__device__ float g_scores[NB * NL];
__device__ float g_aw[NB * NL];
__device__ float g_bt[NB * NL];
__device__ float g_btn[NB];
__device__ float g_u[NB * ND];
__device__ float g_v[NB * ND];
__device__ float g_dl[NB * ND];
__device__ float g_lam[NB * NL];
__device__ float g_part[6 * NB * SPLIT * ND];    // kD partials: [k][b][s][d]
__device__ float g_nomp[NB * SPLITE * ND];       // kE nom partials

__device__ __forceinline__ float artanh_c(float x) {
    x = fminf(fmaxf(x, -1.0f + 1e-7f), 1.0f - 1e-7f);
    return atanhf(x);
}

template <int NT>
__device__ __forceinline__ float blk_sum(float v, float* sb) {
    int t = threadIdx.x;
    sb[t] = v; __syncthreads();
#pragma unroll
    for (int s = NT / 2; s > 0; s >>= 1) {
        if (t < s) sb[t] += sb[t + s];
        __syncthreads();
    }
    float r = sb[0]; __syncthreads();
    return r;
}

template <int NT>
__device__ __forceinline__ float blk_max(float v, float* sb) {
    int t = threadIdx.x;
    sb[t] = v; __syncthreads();
#pragma unroll
    for (int s = NT / 2; s > 0; s >>= 1) {
        if (t < s) sb[t] = fmaxf(sb[t], sb[t + s]);
        __syncthreads();
    }
    float r = sb[0]; __syncthreads();
    return r;
}

// ---------------- A: q = query @ W_in^T ----------------
__global__ void kA(const float* __restrict__ query, const float* __restrict__ W_in) {
    int b = threadIdx.x;
    int e = blockIdx.x * 4 + threadIdx.y;
    const float4* q4 = (const float4*)(query + (size_t)b * ND);
    const float4* w4 = (const float4*)(W_in + (size_t)e * ND);
    float acc = 0.f;
#pragma unroll 4
    for (int k = 0; k < ND / 4; k++) {
        float4 a = q4[k], w = w4[k];
        acc += a.x * w.x + a.y * w.y + a.z * w.z + a.w * w.w;
    }
    g_combined[(size_t)b * 2 * ND + ND + e] = acc;
}

// ---------------- B: scores[b,l] = dot(q[b], ctx[b,l,:]) ----------------
__global__ void kB(const float* __restrict__ ctx, int b0) {
    __shared__ float sq[ND];
    int b = b0 + blockIdx.y;
    int warp = threadIdx.x >> 5, lane = threadIdx.x & 31;
    ((float4*)sq)[threadIdx.x] = ((const float4*)(g_combined + (size_t)b * 2 * ND + ND))[threadIdx.x];
    __syncthreads();
    int l = blockIdx.x * 8 + warp;
    const float4* c4 = (const float4*)(ctx + ((size_t)(b * NL + l)) * ND);
    const float4* s4 = (const float4*)sq;
    float acc = 0.f;
#pragma unroll
    for (int k = 0; k < 8; k++) {
        int i = k * 32 + lane;
        float4 cv = c4[i], qv = s4[i];
        acc += cv.x * qv.x + cv.y * qv.y + cv.z * qv.z + cv.w * qv.w;
    }
#pragma unroll
    for (int o = 16; o > 0; o >>= 1) acc += __shfl_down_sync(0xffffffffu, acc, o);
    if (lane == 0) g_scores[b * NL + l] = acc;
}

// ---------------- C: softmax + expmap0/project (aw), bt ----------------
__global__ void kC(const float* __restrict__ dt, const float* __restrict__ cp,
                   const float* __restrict__ ab, float* __restrict__ out_aw, int b0) {
    __shared__ float sb[1024];
    int b = b0 + blockIdx.x, t = threadIdx.x;
    float c = cp[0], sc = sqrtf(c);
    float maxn = (1.0f - PROJ_EPS) / sc;

    float s = g_scores[b * NL + t];
    float mx = blk_max<1024>(s, sb);
    float e = expf(s - mx);
    float sum = blk_sum<1024>(e, sb);
    float aw = e / sum;

    float n = fmaxf(sqrtf(blk_sum<1024>(aw * aw, sb)), EPSF);
    float awh = tanhf(sc * n) / (sc * n) * aw;
    float nh = fmaxf(sqrtf(blk_sum<1024>(awh * awh, sb)), EPSF);
    if (nh > maxn) awh *= maxn / nh;
    g_aw[b * NL + t] = awh;
    out_aw[b * NL + t] = awh;

    float braw = expf(-ab[b] * dt[b * NL + t]);
    float bn = fmaxf(sqrtf(blk_sum<1024>(braw * braw, sb)), EPSF);
    float bth = tanhf(sc * bn) / (sc * bn) * braw;
    float bh = fmaxf(sqrtf(blk_sum<1024>(bth * bth, sb)), EPSF);
    if (bh > maxn) bth *= maxn / bh;
    g_bt[b * NL + t] = bth;
    if (t == 0) g_btn[b] = fminf(bh, maxn);
}

// ---------------- D1: partial column stats over an l-chunk ----------------
__global__ void kD1(const float* __restrict__ ctx, int b0) {
    __shared__ float saw[CH_D], sbt[CH_D];
    int b = b0 + blockIdx.y, s = blockIdx.x, t = threadIdx.x;
    int l0 = s * CH_D;
    if (t < CH_D) { saw[t] = g_aw[b * NL + l0 + t]; sbt[t] = g_bt[b * NL + l0 + t]; }
    __syncthreads();
    const float4* cb = (const float4*)(ctx + ((size_t)(b * NL + l0)) * ND) + t;

    float4 sx2 = {0,0,0,0}, swx2 = {0,0,0,0};
    float4 s2p = {0,0,0,0}, s2n = {0,0,0,0}, sxp = {0,0,0,0}, sxn = {0,0,0,0};

#pragma unroll 4
    for (int ll = 0; ll < CH_D; ll++) {
        float4 x = cb[(size_t)ll * (ND / 4)];
        float a = saw[ll], bt = sbt[ll];
        {
            float ax = a * x.x, g = bt * ax;
            sx2.x += x.x * x.x; swx2.x += ax * ax;
            if (g > 0.f) { s2p.x += g * g; sxp.x += ax * g; }
            else if (g < 0.f) { s2n.x += g * g; sxn.x += ax * g; }
        }
        {
            float ax = a * x.y, g = bt * ax;
            sx2.y += x.y * x.y; swx2.y += ax * ax;
            if (g > 0.f) { s2p.y += g * g; sxp.y += ax * g; }
            else if (g < 0.f) { s2n.y += g * g; sxn.y += ax * g; }
        }
        {
            float ax = a * x.z, g = bt * ax;
            sx2.z += x.z * x.z; swx2.z += ax * ax;
            if (g > 0.f) { s2p.z += g * g; sxp.z += ax * g; }
            else if (g < 0.f) { s2n.z += g * g; sxn.z += ax * g; }
        }
        {
            float ax = a * x.w, g = bt * ax;
            sx2.w += x.w * x.w; swx2.w += ax * ax;
            if (g > 0.f) { s2p.w += g * g; sxp.w += ax * g; }
            else if (g < 0.f) { s2n.w += g * g; sxn.w += ax * g; }
        }
    }
    size_t base = ((size_t)(b * SPLIT + s)) * ND;
    size_t stride = (size_t)NB * SPLIT * ND;
    ((float4*)(g_part + 0 * stride + base))[t] = sx2;
    ((float4*)(g_part + 1 * stride + base))[t] = swx2;
    ((float4*)(g_part + 2 * stride + base))[t] = s2p;
    ((float4*)(g_part + 3 * stride + base))[t] = s2n;
    ((float4*)(g_part + 4 * stride + base))[t] = sxp;
    ((float4*)(g_part + 5 * stride + base))[t] = sxn;
}

// ---------------- Df: finalize per-(b,d) scalars u, v, delta ----------------
__global__ void kDf(const float* __restrict__ cp, const float* __restrict__ ae, int b0) {
    int b = b0 + blockIdx.y;
    int d = blockIdx.x * 256 + threadIdx.x;
    size_t stride = (size_t)NB * SPLIT * ND;
    float sx2 = 0.f, swx2 = 0.f, s2p = 0.f, s2n = 0.f, sxp = 0.f, sxn = 0.f;
#pragma unroll
    for (int s = 0; s < SPLIT; s++) {
        size_t base = ((size_t)(b * SPLIT + s)) * ND + d;
        sx2  += g_part[0 * stride + base];
        swx2 += g_part[1 * stride + base];
        s2p  += g_part[2 * stride + base];
        s2n  += g_part[3 * stride + base];
        sxp  += g_part[4 * stride + base];
        sxn  += g_part[5 * stride + base];
    }

    float c = cp[0], sc = sqrtf(c);
    float maxn = (1.0f - PROJ_EPS) / sc;

    float xn   = fmaxf(sqrtf(sx2), EPSF);
    float wxnr = sqrtf(swx2);
    float wxn  = fmaxf(wxnr, EPSF);
    float s1 = tanhf(wxn / xn * artanh_c(sc * xn)) / (wxn * sc);
    float n1 = fmaxf(fabsf(s1) * wxnr, EPSF);
    float alpha = s1 * (n1 > maxn ? maxn / n1 : 1.0f);
    float nmixr = fabsf(alpha) * wxnr;

    float aeb = ae[b];
    float xn7 = fmaxf(nmixr, EPSF);
    float wxn7 = fmaxf(fabsf(aeb) * nmixr, EPSF);
    float t7 = tanhf(wxn7 / xn7 * artanh_c(sc * xn7)) / (wxn7 * sc);
    float n7 = fmaxf(fabsf(t7 * aeb) * nmixr, EPSF);
    float T = t7 * aeb * alpha * (n7 > maxn ? maxn / n7 : 1.0f);

    float m8r = sqrtf(s2p + s2n);
    float xn8 = g_btn[b];
    float wxn8 = fmaxf(fabsf(T) * m8r, EPSF);
    float t8 = tanhf(wxn8 / xn8 * artanh_c(sc * xn8)) / (wxn8 * sc);
    float dpre = t8 * T;
    float n8 = fmaxf(fabsf(dpre) * m8r, EPSF);
    float dl = dpre * (n8 > maxn ? maxn / n8 : 1.0f);

    float x2 = alpha * alpha * swx2;
    bool pos = (dl > 0.f);
    float S2 = pos ? s2p : s2n;
    float SX = pos ? sxp : sxn;
    float y2 = dl * dl * S2;
    float xy = alpha * dl * SX;
    float A  = 1.0f + 2.0f * c * xy + c * y2;
    float Bc = 1.0f - c * x2;
    float den = fmaxf(1.0f + 2.0f * c * xy + c * c * x2 * y2, EPSF);
    float nn2 = (A * A * x2 + 2.0f * A * Bc * xy + Bc * Bc * y2) / (den * den);
    float n10 = fmaxf(sqrtf(fmaxf(nn2, 0.f)), EPSF);
    float p10 = (n10 > maxn) ? maxn / n10 : 1.0f;

    g_u[b * ND + d]  = p10 * A * alpha / den;
    g_v[b * ND + d]  = p10 * Bc * dl / den;
    g_dl[b * ND + d] = dl;
}

// ---------------- E (fused): lambda[b,l] + nom partials in ONE ctx pass ----------------
// block = (l-chunk s, batch b). 256 threads own the whole 1024-d row (float4 each).
__global__ void kE(const float* __restrict__ ctx, const float* __restrict__ cp, int b0) {
    __shared__ float saw[CH_E], sbt[CH_E];
    __shared__ float swsum[8];
    int b = b0 + blockIdx.y, s = blockIdx.x, t = threadIdx.x;
    int warp = t >> 5, lane = t & 31;
    int l0 = s * CH_E;
    if (t < CH_E) { saw[t] = g_aw[b * NL + l0 + t]; sbt[t] = g_bt[b * NL + l0 + t]; }
    float c = cp[0];
    const float4* cb = (const float4*)(ctx + ((size_t)(b * NL + l0)) * ND) + t;
    float4 u  = ((const float4*)(g_u  + (size_t)b * ND))[t];
    float4 v  = ((const float4*)(g_v  + (size_t)b * ND))[t];
    float4 dl = ((const float4*)(g_dl + (size_t)b * ND))[t];
    __syncthreads();

    float4 nom = {0, 0, 0, 0};
    float4 x = cb[0];
    for (int ll = 0; ll < CH_E; ll++) {
        // prefetch next row early (overlaps the reduction barriers below)
        float4 xn = (ll + 1 < CH_E) ? cb[(size_t)(ll + 1) * (ND / 4)] : make_float4(0, 0, 0, 0);
        float a = saw[ll], bt = sbt[ll];
        float4 m;
        float g;
        g = a * bt * x.x; m.x = u.x * a * x.x + ((dl.x * g) > 0.f ? v.x * g : 0.f);
        g = a * bt * x.y; m.y = u.y * a * x.y + ((dl.y * g) > 0.f ? v.y * g : 0.f);
        g = a * bt * x.z; m.z = u.z * a * x.z + ((dl.z * g) > 0.f ? v.z * g : 0.f);
        g = a * bt * x.w; m.w = u.w * a * x.w + ((dl.w * g) > 0.f ? v.w * g : 0.f);
        float ssum = m.x * m.x + m.y * m.y + m.z * m.z + m.w * m.w;
#pragma unroll
        for (int o = 16; o > 0; o >>= 1) ssum += __shfl_xor_sync(0xffffffffu, ssum, o);
        if (lane == 0) swsum[warp] = ssum;
        __syncthreads();
        float tot = swsum[0] + swsum[1] + swsum[2] + swsum[3]
                  + swsum[4] + swsum[5] + swsum[6] + swsum[7];
        float lam = 2.0f / fmaxf(1.0f - c * tot, EPSF);
        nom.x += lam * m.x; nom.y += lam * m.y; nom.z += lam * m.z; nom.w += lam * m.w;
        if (t == 0) g_lam[b * NL + l0 + ll] = lam;
        x = xn;
        __syncthreads();   // protect swsum before next iteration writes
    }
    ((float4*)(g_nomp + ((size_t)(b * SPLITE + s)) * ND))[t] = nom;
}

// ---------------- F: midpoint epilogue (sums nom partials) ----------------
__global__ void kF(const float* __restrict__ cp) {
    __shared__ float sb[1024];
    int b = blockIdx.x, t = threadIdx.x;
    float c = cp[0], sc = sqrtf(c);
    float maxn = (1.0f - PROJ_EPS) / sc; (void)maxn;
    float lam = g_lam[b * NL + t];
    float den = blk_sum<1024>(lam - 1.0f, sb);
    den = (den >= 0.f) ? fmaxf(den, 1e-10f) : fminf(den, -1e-10f);

    float nom = 0.f;
#pragma unroll
    for (int s = 0; s < SPLITE; s++)
        nom += g_nomp[((size_t)(b * SPLITE + s)) * ND + t];

    float tm = nom / den;
    float nr = sqrtf(blk_sum<1024>(tm * tm, sb));
    float n = fmaxf(nr, EPSF);
    float cf = tanhf(0.5f * artanh_c(sc * n)) / (sc * n);
    float nf = fmaxf(fabsf(cf) * nr, EPSF);
    float lc = artanh_c(sc * nf) / (sc * nf);
    g_combined[(size_t)b * 2 * ND + t] = lc * cf * tm;
}

// ---------------- G: out = tanh(combined @ W_out^T) ----------------
__global__ void kG(const float* __restrict__ W_out, float* __restrict__ out) {
    int b = threadIdx.x;
    int d = blockIdx.x * 4 + threadIdx.y;
    const float4* cb4 = (const float4*)(g_combined + (size_t)b * 2 * ND);
    const float4* w4  = (const float4*)(W_out + (size_t)d * 2 * ND);
    float acc = 0.f;
#pragma unroll 4
    for (int k = 0; k < 2 * ND / 4; k++) {
        float4 a = cb4[k], w = w4[k];
        acc += a.x * w.x + a.y * w.y + a.z * w.z + a.w * w.w;
    }
    out[b * ND + d] = tanhf(acc);
}

// ---------------- launch: L2-resident chunks of BC batches ----------------
extern "C" void kernel_launch(void* const* d_in, const int* in_sizes, int n_in,
                              void* d_out, int out_size) {
    const float* query = (const float*)d_in[0];
    const float* ctx   = (const float*)d_in[1];
    const float* dt    = (const float*)d_in[2];
    const float* cp    = (const float*)d_in[3];
    const float* W_in  = (const float*)d_in[4];
    const float* W_out = (const float*)d_in[5];
    const float* ae    = (const float*)d_in[6];
    const float* ab    = (const float*)d_in[7];
    float* out = (float*)d_out;

    kA<<<ND / 4, dim3(64, 4)>>>(query, W_in);
    for (int chk = 0; chk < NCHUNK; chk++) {
        int b0 = chk * BC;
        kB <<<dim3(NL / 8, BC), 256>>>(ctx, b0);
        kC <<<BC, 1024>>>(dt, cp, ab, out + NB * ND, b0);
        kD1<<<dim3(SPLIT, BC), 256>>>(ctx, b0);
        kDf<<<dim3(ND / 256, BC), 256>>>(cp, ae, b0);
        kE <<<dim3(SPLITE, BC), 256>>>(ctx, cp, b0);
    }
    kF<<<NB, 1024>>>(cp);
    kG<<<ND / 4, dim3(64, 4)>>>(W_out, out);
}

// round 4
// speedup vs baseline: 1.2205x; 1.2205x over previous
#include <cuda_runtime.h>
#include <math.h>

#define NB 64
#define NL 1024
#define ND 1024
#define SPLIT 32               // kD l-splits  (CH_D = 32)
#define CH_D (NL / SPLIT)
#define SPLITE 32              // kE l-splits  (CH_E = 32)
#define CH_E (NL / SPLITE)
#define EPSF 1e-15f
#define PROJ_EPS 4e-3f

// ---------------- scratch (device globals) ----------------
__device__ float g_combined[NB * 2 * ND];   // [b,0:D)=mixl, [b,D:2D)=q
__device__ float g_scores[NB * NL];
__device__ float g_aw[NB * NL];
__device__ float g_bt[NB * NL];
__device__ float g_btn[NB];
__device__ float g_u[NB * ND];
__device__ float g_v[NB * ND];
__device__ float g_dl[NB * ND];
__device__ float g_lam[NB * NL];
__device__ float g_part[6 * NB * SPLIT * ND];    // kD partials: [k][b][s][d]
__device__ float g_nomp[NB * SPLITE * ND];       // kE nom partials

__device__ __forceinline__ float artanh_c(float x) {
    x = fminf(fmaxf(x, -1.0f + 1e-7f), 1.0f - 1e-7f);
    return atanhf(x);
}

template <int NT>
__device__ __forceinline__ float blk_sum(float v, float* sb) {
    int t = threadIdx.x;
    sb[t] = v; __syncthreads();
#pragma unroll
    for (int s = NT / 2; s > 0; s >>= 1) {
        if (t < s) sb[t] += sb[t + s];
        __syncthreads();
    }
    float r = sb[0]; __syncthreads();
    return r;
}

template <int NT>
__device__ __forceinline__ float blk_max(float v, float* sb) {
    int t = threadIdx.x;
    sb[t] = v; __syncthreads();
#pragma unroll
    for (int s = NT / 2; s > 0; s >>= 1) {
        if (t < s) sb[t] = fmaxf(sb[t], sb[t + s]);
        __syncthreads();
    }
    float r = sb[0]; __syncthreads();
    return r;
}

// ---------------- A: q = query @ W_in^T ----------------
__global__ void kA(const float* __restrict__ query, const float* __restrict__ W_in) {
    int b = threadIdx.x;
    int e = blockIdx.x * 4 + threadIdx.y;
    const float4* q4 = (const float4*)(query + (size_t)b * ND);
    const float4* w4 = (const float4*)(W_in + (size_t)e * ND);
    float acc = 0.f;
#pragma unroll 4
    for (int k = 0; k < ND / 4; k++) {
        float4 a = q4[k], w = w4[k];
        acc += a.x * w.x + a.y * w.y + a.z * w.z + a.w * w.w;
    }
    g_combined[(size_t)b * 2 * ND + ND + e] = acc;
}

// ---------------- B: scores[b,l] = dot(q[b], ctx[b,l,:]) ----------------
__global__ void kB(const float* __restrict__ ctx) {
    __shared__ float sq[ND];
    int b = blockIdx.y;
    int warp = threadIdx.x >> 5, lane = threadIdx.x & 31;
    ((float4*)sq)[threadIdx.x] = ((const float4*)(g_combined + (size_t)b * 2 * ND + ND))[threadIdx.x];
    __syncthreads();
    int l = blockIdx.x * 8 + warp;
    const float4* c4 = (const float4*)(ctx + ((size_t)(b * NL + l)) * ND);
    const float4* s4 = (const float4*)sq;
    float acc = 0.f;
#pragma unroll
    for (int k = 0; k < 8; k++) {
        int i = k * 32 + lane;
        float4 cv = c4[i], qv = s4[i];
        acc += cv.x * qv.x + cv.y * qv.y + cv.z * qv.z + cv.w * qv.w;
    }
#pragma unroll
    for (int o = 16; o > 0; o >>= 1) acc += __shfl_down_sync(0xffffffffu, acc, o);
    if (lane == 0) g_scores[b * NL + l] = acc;
}

// ---------------- C: softmax + expmap0/project (aw), bt ----------------
__global__ void kC(const float* __restrict__ dt, const float* __restrict__ cp,
                   const float* __restrict__ ab, float* __restrict__ out_aw) {
    __shared__ float sb[1024];
    int b = blockIdx.x, t = threadIdx.x;
    float c = cp[0], sc = sqrtf(c);
    float maxn = (1.0f - PROJ_EPS) / sc;

    float s = g_scores[b * NL + t];
    float mx = blk_max<1024>(s, sb);
    float e = expf(s - mx);
    float sum = blk_sum<1024>(e, sb);
    float aw = e / sum;

    float n = fmaxf(sqrtf(blk_sum<1024>(aw * aw, sb)), EPSF);
    float awh = tanhf(sc * n) / (sc * n) * aw;
    float nh = fmaxf(sqrtf(blk_sum<1024>(awh * awh, sb)), EPSF);
    if (nh > maxn) awh *= maxn / nh;
    g_aw[b * NL + t] = awh;
    out_aw[b * NL + t] = awh;

    float braw = expf(-ab[b] * dt[b * NL + t]);
    float bn = fmaxf(sqrtf(blk_sum<1024>(braw * braw, sb)), EPSF);
    float bth = tanhf(sc * bn) / (sc * bn) * braw;
    float bh = fmaxf(sqrtf(blk_sum<1024>(bth * bth, sb)), EPSF);
    if (bh > maxn) bth *= maxn / bh;
    g_bt[b * NL + t] = bth;
    if (t == 0) g_btn[b] = fminf(bh, maxn);
}

// ---------------- D1: partial column stats over an l-chunk ----------------
// grid (SPLIT, NB) = 2048 blocks, 256 threads; thread owns 4 d via float4.
__global__ void kD1(const float* __restrict__ ctx) {
    __shared__ float saw[CH_D], sbt[CH_D];
    int b = blockIdx.y, s = blockIdx.x, t = threadIdx.x;
    int l0 = s * CH_D;
    if (t < CH_D) { saw[t] = g_aw[b * NL + l0 + t]; sbt[t] = g_bt[b * NL + l0 + t]; }
    __syncthreads();
    const float4* cb = (const float4*)(ctx + ((size_t)(b * NL + l0)) * ND) + t;

    float4 sx2 = {0,0,0,0}, swx2 = {0,0,0,0};
    float4 s2p = {0,0,0,0}, s2n = {0,0,0,0}, sxp = {0,0,0,0}, sxn = {0,0,0,0};

#pragma unroll 4
    for (int ll = 0; ll < CH_D; ll++) {
        float4 x = cb[(size_t)ll * (ND / 4)];
        float a = saw[ll], bt = sbt[ll];
        {
            float ax = a * x.x, g = bt * ax;
            sx2.x += x.x * x.x; swx2.x += ax * ax;
            if (g > 0.f) { s2p.x += g * g; sxp.x += ax * g; }
            else if (g < 0.f) { s2n.x += g * g; sxn.x += ax * g; }
        }
        {
            float ax = a * x.y, g = bt * ax;
            sx2.y += x.y * x.y; swx2.y += ax * ax;
            if (g > 0.f) { s2p.y += g * g; sxp.y += ax * g; }
            else if (g < 0.f) { s2n.y += g * g; sxn.y += ax * g; }
        }
        {
            float ax = a * x.z, g = bt * ax;
            sx2.z += x.z * x.z; swx2.z += ax * ax;
            if (g > 0.f) { s2p.z += g * g; sxp.z += ax * g; }
            else if (g < 0.f) { s2n.z += g * g; sxn.z += ax * g; }
        }
        {
            float ax = a * x.w, g = bt * ax;
            sx2.w += x.w * x.w; swx2.w += ax * ax;
            if (g > 0.f) { s2p.w += g * g; sxp.w += ax * g; }
            else if (g < 0.f) { s2n.w += g * g; sxn.w += ax * g; }
        }
    }
    size_t base = ((size_t)(b * SPLIT + s)) * ND;
    size_t stride = (size_t)NB * SPLIT * ND;
    ((float4*)(g_part + 0 * stride + base))[t] = sx2;
    ((float4*)(g_part + 1 * stride + base))[t] = swx2;
    ((float4*)(g_part + 2 * stride + base))[t] = s2p;
    ((float4*)(g_part + 3 * stride + base))[t] = s2n;
    ((float4*)(g_part + 4 * stride + base))[t] = sxp;
    ((float4*)(g_part + 5 * stride + base))[t] = sxn;
}

// ---------------- Df: finalize per-(b,d) scalars u, v, delta ----------------
__global__ void kDf(const float* __restrict__ cp, const float* __restrict__ ae) {
    int b = blockIdx.y;
    int d = blockIdx.x * 256 + threadIdx.x;
    size_t stride = (size_t)NB * SPLIT * ND;
    float sx2 = 0.f, swx2 = 0.f, s2p = 0.f, s2n = 0.f, sxp = 0.f, sxn = 0.f;
#pragma unroll
    for (int s = 0; s < SPLIT; s++) {
        size_t base = ((size_t)(b * SPLIT + s)) * ND + d;
        sx2  += g_part[0 * stride + base];
        swx2 += g_part[1 * stride + base];
        s2p  += g_part[2 * stride + base];
        s2n  += g_part[3 * stride + base];
        sxp  += g_part[4 * stride + base];
        sxn  += g_part[5 * stride + base];
    }

    float c = cp[0], sc = sqrtf(c);
    float maxn = (1.0f - PROJ_EPS) / sc;

    float xn   = fmaxf(sqrtf(sx2), EPSF);
    float wxnr = sqrtf(swx2);
    float wxn  = fmaxf(wxnr, EPSF);
    float s1 = tanhf(wxn / xn * artanh_c(sc * xn)) / (wxn * sc);
    float n1 = fmaxf(fabsf(s1) * wxnr, EPSF);
    float alpha = s1 * (n1 > maxn ? maxn / n1 : 1.0f);
    float nmixr = fabsf(alpha) * wxnr;

    float aeb = ae[b];
    float xn7 = fmaxf(nmixr, EPSF);
    float wxn7 = fmaxf(fabsf(aeb) * nmixr, EPSF);
    float t7 = tanhf(wxn7 / xn7 * artanh_c(sc * xn7)) / (wxn7 * sc);
    float n7 = fmaxf(fabsf(t7 * aeb) * nmixr, EPSF);
    float T = t7 * aeb * alpha * (n7 > maxn ? maxn / n7 : 1.0f);

    float m8r = sqrtf(s2p + s2n);
    float xn8 = g_btn[b];
    float wxn8 = fmaxf(fabsf(T) * m8r, EPSF);
    float t8 = tanhf(wxn8 / xn8 * artanh_c(sc * xn8)) / (wxn8 * sc);
    float dpre = t8 * T;
    float n8 = fmaxf(fabsf(dpre) * m8r, EPSF);
    float dl = dpre * (n8 > maxn ? maxn / n8 : 1.0f);

    float x2 = alpha * alpha * swx2;
    bool pos = (dl > 0.f);
    float S2 = pos ? s2p : s2n;
    float SX = pos ? sxp : sxn;
    float y2 = dl * dl * S2;
    float xy = alpha * dl * SX;
    float A  = 1.0f + 2.0f * c * xy + c * y2;
    float Bc = 1.0f - c * x2;
    float den = fmaxf(1.0f + 2.0f * c * xy + c * c * x2 * y2, EPSF);
    float nn2 = (A * A * x2 + 2.0f * A * Bc * xy + Bc * Bc * y2) / (den * den);
    float n10 = fmaxf(sqrtf(fmaxf(nn2, 0.f)), EPSF);
    float p10 = (n10 > maxn) ? maxn / n10 : 1.0f;

    g_u[b * ND + d]  = p10 * A * alpha / den;
    g_v[b * ND + d]  = p10 * Bc * dl / den;
    g_dl[b * ND + d] = dl;
}

// ---------------- E (fused): lambda[b,l] + nom partials in ONE ctx pass ----------------
// grid (SPLITE, NB) = 2048 blocks, 256 threads own the whole 1024-d row (float4 each).
__global__ void kE(const float* __restrict__ ctx, const float* __restrict__ cp) {
    __shared__ float saw[CH_E], sbt[CH_E];
    __shared__ float swsum[8];
    int b = blockIdx.y, s = blockIdx.x, t = threadIdx.x;
    int warp = t >> 5, lane = t & 31;
    int l0 = s * CH_E;
    if (t < CH_E) { saw[t] = g_aw[b * NL + l0 + t]; sbt[t] = g_bt[b * NL + l0 + t]; }
    float c = cp[0];
    const float4* cb = (const float4*)(ctx + ((size_t)(b * NL + l0)) * ND) + t;
    float4 u  = ((const float4*)(g_u  + (size_t)b * ND))[t];
    float4 v  = ((const float4*)(g_v  + (size_t)b * ND))[t];
    float4 dl = ((const float4*)(g_dl + (size_t)b * ND))[t];
    __syncthreads();

    float4 nom = {0, 0, 0, 0};
    float4 x = cb[0];
    for (int ll = 0; ll < CH_E; ll++) {
        float4 xn = (ll + 1 < CH_E) ? cb[(size_t)(ll + 1) * (ND / 4)] : make_float4(0, 0, 0, 0);
        float a = saw[ll], bt = sbt[ll];
        float4 m;
        float g;
        g = a * bt * x.x; m.x = u.x * a * x.x + ((dl.x * g) > 0.f ? v.x * g : 0.f);
        g = a * bt * x.y; m.y = u.y * a * x.y + ((dl.y * g) > 0.f ? v.y * g : 0.f);
        g = a * bt * x.z; m.z = u.z * a * x.z + ((dl.z * g) > 0.f ? v.z * g : 0.f);
        g = a * bt * x.w; m.w = u.w * a * x.w + ((dl.w * g) > 0.f ? v.w * g : 0.f);
        float ssum = m.x * m.x + m.y * m.y + m.z * m.z + m.w * m.w;
#pragma unroll
        for (int o = 16; o > 0; o >>= 1) ssum += __shfl_xor_sync(0xffffffffu, ssum, o);
        if (lane == 0) swsum[warp] = ssum;
        __syncthreads();
        float tot = swsum[0] + swsum[1] + swsum[2] + swsum[3]
                  + swsum[4] + swsum[5] + swsum[6] + swsum[7];
        float lam = 2.0f / fmaxf(1.0f - c * tot, EPSF);
        nom.x += lam * m.x; nom.y += lam * m.y; nom.z += lam * m.z; nom.w += lam * m.w;
        if (t == 0) g_lam[b * NL + l0 + ll] = lam;
        x = xn;
        __syncthreads();   // protect swsum before next iteration writes
    }
    ((float4*)(g_nomp + ((size_t)(b * SPLITE + s)) * ND))[t] = nom;
}

// ---------------- F: midpoint epilogue (sums nom partials) ----------------
__global__ void kF(const float* __restrict__ cp) {
    __shared__ float sb[1024];
    int b = blockIdx.x, t = threadIdx.x;
    float c = cp[0], sc = sqrtf(c);
    float lam = g_lam[b * NL + t];
    float den = blk_sum<1024>(lam - 1.0f, sb);
    den = (den >= 0.f) ? fmaxf(den, 1e-10f) : fminf(den, -1e-10f);

    float nom = 0.f;
#pragma unroll
    for (int s = 0; s < SPLITE; s++)
        nom += g_nomp[((size_t)(b * SPLITE + s)) * ND + t];

    float tm = nom / den;
    float nr = sqrtf(blk_sum<1024>(tm * tm, sb));
    float n = fmaxf(nr, EPSF);
    float cf = tanhf(0.5f * artanh_c(sc * n)) / (sc * n);
    float nf = fmaxf(fabsf(cf) * nr, EPSF);
    float lc = artanh_c(sc * nf) / (sc * nf);
    g_combined[(size_t)b * 2 * ND + t] = lc * cf * tm;
}

// ---------------- G: out = tanh(combined @ W_out^T) ----------------
__global__ void kG(const float* __restrict__ W_out, float* __restrict__ out) {
    int b = threadIdx.x;
    int d = blockIdx.x * 4 + threadIdx.y;
    const float4* cb4 = (const float4*)(g_combined + (size_t)b * 2 * ND);
    const float4* w4  = (const float4*)(W_out + (size_t)d * 2 * ND);
    float acc = 0.f;
#pragma unroll 4
    for (int k = 0; k < 2 * ND / 4; k++) {
        float4 a = cb4[k], w = w4[k];
        acc += a.x * w.x + a.y * w.y + a.z * w.z + a.w * w.w;
    }
    out[b * ND + d] = tanhf(acc);
}

// ---------------- launch ----------------
extern "C" void kernel_launch(void* const* d_in, const int* in_sizes, int n_in,
                              void* d_out, int out_size) {
    const float* query = (const float*)d_in[0];
    const float* ctx   = (const float*)d_in[1];
    const float* dt    = (const float*)d_in[2];
    const float* cp    = (const float*)d_in[3];
    const float* W_in  = (const float*)d_in[4];
    const float* W_out = (const float*)d_in[5];
    const float* ae    = (const float*)d_in[6];
    const float* ab    = (const float*)d_in[7];
    float* out = (float*)d_out;

    kA <<<ND / 4, dim3(64, 4)>>>(query, W_in);
    kB <<<dim3(NL / 8, NB), 256>>>(ctx);
    kC <<<NB, 1024>>>(dt, cp, ab, out + NB * ND);
    kD1<<<dim3(SPLIT, NB), 256>>>(ctx);
    kDf<<<dim3(ND / 256, NB), 256>>>(cp, ae);
    kE <<<dim3(SPLITE, NB), 256>>>(ctx, cp);
    kF <<<NB, 1024>>>(cp);
    kG <<<ND / 4, dim3(64, 4)>>>(W_out, out);
}

// round 5
// speedup vs baseline: 1.3170x; 1.0791x over previous
#include <cuda_runtime.h>
#include <math.h>

#define NB 64
#define NL 1024
#define ND 1024
#define SPLIT 32               // kD l-splits  (CH_D = 32)
#define CH_D (NL / SPLIT)
#define SPLITE 32              // kE l-splits  (CH_E = 32)
#define CH_E (NL / SPLITE)
#define EPSF 1e-15f
#define PROJ_EPS 4e-3f

// ---------------- scratch (device globals) ----------------
__device__ float g_combined[NB * 2 * ND];   // [b,0:D)=mixl, [b,D:2D)=q
__device__ float g_scores[NB * NL];
__device__ float g_aw[NB * NL];
__device__ float g_bt[NB * NL];
__device__ float g_btn[NB];
__device__ float g_u[NB * ND];
__device__ float g_v[NB * ND];
__device__ float g_dl[NB * ND];
__device__ float g_lam[NB * NL];
__device__ float g_part[6 * NB * SPLIT * ND];    // kD partials: [k][b][s][d]
__device__ float g_nomp[NB * SPLITE * ND];       // kE nom partials

__device__ __forceinline__ float artanh_c(float x) {
    x = fminf(fmaxf(x, -1.0f + 1e-7f), 1.0f - 1e-7f);
    return atanhf(x);
}

template <int NT>
__device__ __forceinline__ float blk_sum(float v, float* sb) {
    int t = threadIdx.x;
    sb[t] = v; __syncthreads();
#pragma unroll
    for (int s = NT / 2; s > 0; s >>= 1) {
        if (t < s) sb[t] += sb[t + s];
        __syncthreads();
    }
    float r = sb[0]; __syncthreads();
    return r;
}

template <int NT>
__device__ __forceinline__ float blk_max(float v, float* sb) {
    int t = threadIdx.x;
    sb[t] = v; __syncthreads();
#pragma unroll
    for (int s = NT / 2; s > 0; s >>= 1) {
        if (t < s) sb[t] = fmaxf(sb[t], sb[t + s]);
        __syncthreads();
    }
    float r = sb[0]; __syncthreads();
    return r;
}

// ---------------- A: q = query @ W_in^T ----------------
__global__ void kA(const float* __restrict__ query, const float* __restrict__ W_in) {
    int b = threadIdx.x;
    int e = blockIdx.x * 4 + threadIdx.y;
    const float4* q4 = (const float4*)(query + (size_t)b * ND);
    const float4* w4 = (const float4*)(W_in + (size_t)e * ND);
    float acc = 0.f;
#pragma unroll 4
    for (int k = 0; k < ND / 4; k++) {
        float4 a = q4[k], w = w4[k];
        acc += a.x * w.x + a.y * w.y + a.z * w.z + a.w * w.w;
    }
    g_combined[(size_t)b * 2 * ND + ND + e] = acc;
}

// ---------------- B: scores[b,l] = dot(q[b], ctx[b,l,:]) ----------------
__global__ void kB(const float* __restrict__ ctx) {
    __shared__ float sq[ND];
    int b = blockIdx.y;
    int warp = threadIdx.x >> 5, lane = threadIdx.x & 31;
    ((float4*)sq)[threadIdx.x] = ((const float4*)(g_combined + (size_t)b * 2 * ND + ND))[threadIdx.x];
    __syncthreads();
    int l = blockIdx.x * 8 + warp;
    const float4* c4 = (const float4*)(ctx + ((size_t)(b * NL + l)) * ND);
    const float4* s4 = (const float4*)sq;
    float acc = 0.f;
#pragma unroll
    for (int k = 0; k < 8; k++) {
        int i = k * 32 + lane;
        float4 cv = c4[i], qv = s4[i];
        acc += cv.x * qv.x + cv.y * qv.y + cv.z * qv.z + cv.w * qv.w;
    }
#pragma unroll
    for (int o = 16; o > 0; o >>= 1) acc += __shfl_down_sync(0xffffffffu, acc, o);
    if (lane == 0) g_scores[b * NL + l] = acc;
}

// ---------------- C: softmax + expmap0/project (aw), bt ----------------
__global__ void kC(const float* __restrict__ dt, const float* __restrict__ cp,
                   const float* __restrict__ ab, float* __restrict__ out_aw) {
    __shared__ float sb[1024];
    int b = blockIdx.x, t = threadIdx.x;
    float c = cp[0], sc = sqrtf(c);
    float maxn = (1.0f - PROJ_EPS) / sc;

    float s = g_scores[b * NL + t];
    float mx = blk_max<1024>(s, sb);
    float e = expf(s - mx);
    float sum = blk_sum<1024>(e, sb);
    float aw = e / sum;

    float n = fmaxf(sqrtf(blk_sum<1024>(aw * aw, sb)), EPSF);
    float awh = tanhf(sc * n) / (sc * n) * aw;
    float nh = fmaxf(sqrtf(blk_sum<1024>(awh * awh, sb)), EPSF);
    if (nh > maxn) awh *= maxn / nh;
    g_aw[b * NL + t] = awh;
    out_aw[b * NL + t] = awh;

    float braw = expf(-ab[b] * dt[b * NL + t]);
    float bn = fmaxf(sqrtf(blk_sum<1024>(braw * braw, sb)), EPSF);
    float bth = tanhf(sc * bn) / (sc * bn) * braw;
    float bh = fmaxf(sqrtf(blk_sum<1024>(bth * bth, sb)), EPSF);
    if (bh > maxn) bth *= maxn / bh;
    g_bt[b * NL + t] = bth;
    if (t == 0) g_btn[b] = fminf(bh, maxn);
}

// ---------------- D1: partial column stats over an l-chunk (branchless) ----------------
// Identity: sign(g)=sign(x) since aw,bt>0. All six stats are weighted sums of
// x2 and x2p = x2*[x>0]:  swx2: a^2, s2p/s2n: a^2 b^2, sxp/sxn: a^2 b.
__global__ void __launch_bounds__(256) kD1(const float* __restrict__ ctx) {
    __shared__ float sc1[CH_D], sc2[CH_D], sc3[CH_D];
    int b = NB - 1 - blockIdx.y;       // reverse order: reuse L2 tail from kB
    int s = blockIdx.x, t = threadIdx.x;
    int l0 = s * CH_D;
    if (t < CH_D) {
        float a = g_aw[b * NL + l0 + t];
        float bt = g_bt[b * NL + l0 + t];
        float a2 = a * a;
        sc1[t] = a2;
        sc2[t] = a2 * bt * bt;
        sc3[t] = a2 * bt;
    }
    __syncthreads();
    const float4* cb = (const float4*)(ctx + ((size_t)(b * NL + l0)) * ND) + t;

    float4 sx2 = {0,0,0,0}, swx2 = {0,0,0,0};
    float4 s2p = {0,0,0,0}, s2n = {0,0,0,0}, sxp = {0,0,0,0}, sxn = {0,0,0,0};

#pragma unroll 4
    for (int ll = 0; ll < CH_D; ll++) {
        float4 x = cb[(size_t)ll * (ND / 4)];
        float c1 = sc1[ll], c2 = sc2[ll], c3 = sc3[ll];
        {
            float x2 = x.x * x.x; float xp = (x.x > 0.f) ? x2 : 0.f; float xm = x2 - xp;
            sx2.x += x2; swx2.x = fmaf(c1, x2, swx2.x);
            s2p.x = fmaf(c2, xp, s2p.x); s2n.x = fmaf(c2, xm, s2n.x);
            sxp.x = fmaf(c3, xp, sxp.x); sxn.x = fmaf(c3, xm, sxn.x);
        }
        {
            float x2 = x.y * x.y; float xp = (x.y > 0.f) ? x2 : 0.f; float xm = x2 - xp;
            sx2.y += x2; swx2.y = fmaf(c1, x2, swx2.y);
            s2p.y = fmaf(c2, xp, s2p.y); s2n.y = fmaf(c2, xm, s2n.y);
            sxp.y = fmaf(c3, xp, sxp.y); sxn.y = fmaf(c3, xm, sxn.y);
        }
        {
            float x2 = x.z * x.z; float xp = (x.z > 0.f) ? x2 : 0.f; float xm = x2 - xp;
            sx2.z += x2; swx2.z = fmaf(c1, x2, swx2.z);
            s2p.z = fmaf(c2, xp, s2p.z); s2n.z = fmaf(c2, xm, s2n.z);
            sxp.z = fmaf(c3, xp, sxp.z); sxn.z = fmaf(c3, xm, sxn.z);
        }
        {
            float x2 = x.w * x.w; float xp = (x.w > 0.f) ? x2 : 0.f; float xm = x2 - xp;
            sx2.w += x2; swx2.w = fmaf(c1, x2, swx2.w);
            s2p.w = fmaf(c2, xp, s2p.w); s2n.w = fmaf(c2, xm, s2n.w);
            sxp.w = fmaf(c3, xp, sxp.w); sxn.w = fmaf(c3, xm, sxn.w);
        }
    }
    size_t base = ((size_t)(b * SPLIT + s)) * ND;
    size_t stride = (size_t)NB * SPLIT * ND;
    ((float4*)(g_part + 0 * stride + base))[t] = sx2;
    ((float4*)(g_part + 1 * stride + base))[t] = swx2;
    ((float4*)(g_part + 2 * stride + base))[t] = s2p;
    ((float4*)(g_part + 3 * stride + base))[t] = s2n;
    ((float4*)(g_part + 4 * stride + base))[t] = sxp;
    ((float4*)(g_part + 5 * stride + base))[t] = sxn;
}

// ---------------- Df: finalize per-(b,d) scalars u, v, delta ----------------
__global__ void kDf(const float* __restrict__ cp, const float* __restrict__ ae) {
    int b = blockIdx.y;
    int d = blockIdx.x * 256 + threadIdx.x;
    size_t stride = (size_t)NB * SPLIT * ND;
    float sx2 = 0.f, swx2 = 0.f, s2p = 0.f, s2n = 0.f, sxp = 0.f, sxn = 0.f;
#pragma unroll
    for (int s = 0; s < SPLIT; s++) {
        size_t base = ((size_t)(b * SPLIT + s)) * ND + d;
        sx2  += g_part[0 * stride + base];
        swx2 += g_part[1 * stride + base];
        s2p  += g_part[2 * stride + base];
        s2n  += g_part[3 * stride + base];
        sxp  += g_part[4 * stride + base];
        sxn  += g_part[5 * stride + base];
    }

    float c = cp[0], sc = sqrtf(c);
    float maxn = (1.0f - PROJ_EPS) / sc;

    float xn   = fmaxf(sqrtf(sx2), EPSF);
    float wxnr = sqrtf(swx2);
    float wxn  = fmaxf(wxnr, EPSF);
    float s1 = tanhf(wxn / xn * artanh_c(sc * xn)) / (wxn * sc);
    float n1 = fmaxf(fabsf(s1) * wxnr, EPSF);
    float alpha = s1 * (n1 > maxn ? maxn / n1 : 1.0f);
    float nmixr = fabsf(alpha) * wxnr;

    float aeb = ae[b];
    float xn7 = fmaxf(nmixr, EPSF);
    float wxn7 = fmaxf(fabsf(aeb) * nmixr, EPSF);
    float t7 = tanhf(wxn7 / xn7 * artanh_c(sc * xn7)) / (wxn7 * sc);
    float n7 = fmaxf(fabsf(t7 * aeb) * nmixr, EPSF);
    float T = t7 * aeb * alpha * (n7 > maxn ? maxn / n7 : 1.0f);

    float m8r = sqrtf(s2p + s2n);
    float xn8 = g_btn[b];
    float wxn8 = fmaxf(fabsf(T) * m8r, EPSF);
    float t8 = tanhf(wxn8 / xn8 * artanh_c(sc * xn8)) / (wxn8 * sc);
    float dpre = t8 * T;
    float n8 = fmaxf(fabsf(dpre) * m8r, EPSF);
    float dl = dpre * (n8 > maxn ? maxn / n8 : 1.0f);

    float x2 = alpha * alpha * swx2;
    bool pos = (dl > 0.f);
    float S2 = pos ? s2p : s2n;
    float SX = pos ? sxp : sxn;
    float y2 = dl * dl * S2;
    float xy = alpha * dl * SX;
    float A  = 1.0f + 2.0f * c * xy + c * y2;
    float Bc = 1.0f - c * x2;
    float den = fmaxf(1.0f + 2.0f * c * xy + c * c * x2 * y2, EPSF);
    float nn2 = (A * A * x2 + 2.0f * A * Bc * xy + Bc * Bc * y2) / (den * den);
    float n10 = fmaxf(sqrtf(fmaxf(nn2, 0.f)), EPSF);
    float p10 = (n10 > maxn) ? maxn / n10 : 1.0f;

    g_u[b * ND + d]  = p10 * A * alpha / den;
    g_v[b * ND + d]  = p10 * Bc * dl / den;
    g_dl[b * ND + d] = dl;
}

// ---------------- E (fused): lambda + nom in ONE ctx pass, 2 rows/iter ----------------
// grid (SPLITE, NB) = 2048 blocks, 256 threads own the whole 1024-d row (float4 each).
// Double-buffered warp-sum array -> one barrier per TWO rows.
__global__ void __launch_bounds__(256) kE(const float* __restrict__ ctx, const float* __restrict__ cp) {
    __shared__ float saw[CH_E], sbt[CH_E];
    __shared__ float swsum[2][16];
    int b = NB - 1 - blockIdx.y;       // reverse order: reuse L2 tail from kD1
    int s = blockIdx.x, t = threadIdx.x;
    int warp = t >> 5, lane = t & 31;
    int l0 = s * CH_E;
    if (t < CH_E) { saw[t] = g_aw[b * NL + l0 + t]; sbt[t] = g_bt[b * NL + l0 + t]; }
    float c = cp[0];
    const float4* cb = (const float4*)(ctx + ((size_t)(b * NL + l0)) * ND) + t;
    float4 u  = ((const float4*)(g_u  + (size_t)b * ND))[t];
    float4 v  = ((const float4*)(g_v  + (size_t)b * ND))[t];
    float4 dl = ((const float4*)(g_dl + (size_t)b * ND))[t];
    __syncthreads();

    float4 nom = {0, 0, 0, 0};
    float4 x0 = cb[0];
    float4 x1 = cb[ND / 4];
    for (int ll = 0; ll < CH_E; ll += 2) {
        float4 p0, p1;
        if (ll + 2 < CH_E) {
            p0 = cb[(size_t)(ll + 2) * (ND / 4)];
            p1 = cb[(size_t)(ll + 3) * (ND / 4)];
        } else { p0 = make_float4(0,0,0,0); p1 = p0; }

        float a0 = saw[ll],     bt0 = sbt[ll];
        float a1 = saw[ll + 1], bt1 = sbt[ll + 1];
        float4 m0, m1;
        float g;
        g = a0 * bt0 * x0.x; m0.x = u.x * a0 * x0.x + ((dl.x * g) > 0.f ? v.x * g : 0.f);
        g = a0 * bt0 * x0.y; m0.y = u.y * a0 * x0.y + ((dl.y * g) > 0.f ? v.y * g : 0.f);
        g = a0 * bt0 * x0.z; m0.z = u.z * a0 * x0.z + ((dl.z * g) > 0.f ? v.z * g : 0.f);
        g = a0 * bt0 * x0.w; m0.w = u.w * a0 * x0.w + ((dl.w * g) > 0.f ? v.w * g : 0.f);
        g = a1 * bt1 * x1.x; m1.x = u.x * a1 * x1.x + ((dl.x * g) > 0.f ? v.x * g : 0.f);
        g = a1 * bt1 * x1.y; m1.y = u.y * a1 * x1.y + ((dl.y * g) > 0.f ? v.y * g : 0.f);
        g = a1 * bt1 * x1.z; m1.z = u.z * a1 * x1.z + ((dl.z * g) > 0.f ? v.z * g : 0.f);
        g = a1 * bt1 * x1.w; m1.w = u.w * a1 * x1.w + ((dl.w * g) > 0.f ? v.w * g : 0.f);

        float ss0 = m0.x * m0.x + m0.y * m0.y + m0.z * m0.z + m0.w * m0.w;
        float ss1 = m1.x * m1.x + m1.y * m1.y + m1.z * m1.z + m1.w * m1.w;
#pragma unroll
        for (int o = 16; o > 0; o >>= 1) {
            ss0 += __shfl_xor_sync(0xffffffffu, ss0, o);
            ss1 += __shfl_xor_sync(0xffffffffu, ss1, o);
        }
        int buf = (ll >> 1) & 1;
        if (lane == 0) { swsum[buf][warp * 2] = ss0; swsum[buf][warp * 2 + 1] = ss1; }
        __syncthreads();
        float tot0 = 0.f, tot1 = 0.f;
#pragma unroll
        for (int w = 0; w < 8; w++) { tot0 += swsum[buf][2 * w]; tot1 += swsum[buf][2 * w + 1]; }
        float lam0 = 2.0f / fmaxf(1.0f - c * tot0, EPSF);
        float lam1 = 2.0f / fmaxf(1.0f - c * tot1, EPSF);
        nom.x = fmaf(lam0, m0.x, fmaf(lam1, m1.x, nom.x));
        nom.y = fmaf(lam0, m0.y, fmaf(lam1, m1.y, nom.y));
        nom.z = fmaf(lam0, m0.z, fmaf(lam1, m1.z, nom.z));
        nom.w = fmaf(lam0, m0.w, fmaf(lam1, m1.w, nom.w));
        if (t == 0) { g_lam[b * NL + l0 + ll] = lam0; g_lam[b * NL + l0 + ll + 1] = lam1; }
        x0 = p0; x1 = p1;
        // no second barrier: next iteration writes the other buffer; the write
        // back to THIS buffer happens only after the next iteration's barrier.
    }
    ((float4*)(g_nomp + ((size_t)(b * SPLITE + s)) * ND))[t] = nom;
}

// ---------------- F: midpoint epilogue (sums nom partials) ----------------
__global__ void kF(const float* __restrict__ cp) {
    __shared__ float sb[1024];
    int b = blockIdx.x, t = threadIdx.x;
    float c = cp[0], sc = sqrtf(c);
    float lam = g_lam[b * NL + t];
    float den = blk_sum<1024>(lam - 1.0f, sb);
    den = (den >= 0.f) ? fmaxf(den, 1e-10f) : fminf(den, -1e-10f);

    float nom = 0.f;
#pragma unroll
    for (int s = 0; s < SPLITE; s++)
        nom += g_nomp[((size_t)(b * SPLITE + s)) * ND + t];

    float tm = nom / den;
    float nr = sqrtf(blk_sum<1024>(tm * tm, sb));
    float n = fmaxf(nr, EPSF);
    float cf = tanhf(0.5f * artanh_c(sc * n)) / (sc * n);
    float nf = fmaxf(fabsf(cf) * nr, EPSF);
    float lc = artanh_c(sc * nf) / (sc * nf);
    g_combined[(size_t)b * 2 * ND + t] = lc * cf * tm;
}

// ---------------- G: out = tanh(combined @ W_out^T) ----------------
__global__ void kG(const float* __restrict__ W_out, float* __restrict__ out) {
    int b = threadIdx.x;
    int d = blockIdx.x * 4 + threadIdx.y;
    const float4* cb4 = (const float4*)(g_combined + (size_t)b * 2 * ND);
    const float4* w4  = (const float4*)(W_out + (size_t)d * 2 * ND);
    float acc = 0.f;
#pragma unroll 4
    for (int k = 0; k < 2 * ND / 4; k++) {
        float4 a = cb4[k], w = w4[k];
        acc += a.x * w.x + a.y * w.y + a.z * w.z + a.w * w.w;
    }
    out[b * ND + d] = tanhf(acc);
}

// ---------------- launch ----------------
extern "C" void kernel_launch(void* const* d_in, const int* in_sizes, int n_in,
                              void* d_out, int out_size) {
    const float* query = (const float*)d_in[0];
    const float* ctx   = (const float*)d_in[1];
    const float* dt    = (const float*)d_in[2];
    const float* cp    = (const float*)d_in[3];
    const float* W_in  = (const float*)d_in[4];
    const float* W_out = (const float*)d_in[5];
    const float* ae    = (const float*)d_in[6];
    const float* ab    = (const float*)d_in[7];
    float* out = (float*)d_out;

    kA <<<ND / 4, dim3(64, 4)>>>(query, W_in);
    kB <<<dim3(NL / 8, NB), 256>>>(ctx);
    kC <<<NB, 1024>>>(dt, cp, ab, out + NB * ND);
    kD1<<<dim3(SPLIT, NB), 256>>>(ctx);
    kDf<<<dim3(ND / 256, NB), 256>>>(cp, ae);
    kE <<<dim3(SPLITE, NB), 256>>>(ctx, cp);
    kF <<<NB, 1024>>>(cp);
    kG <<<ND / 4, dim3(64, 4)>>>(W_out, out);
}